// round 17
// baseline (speedup 1.0000x reference)
#include <cuda_runtime.h>
#include <math.h>

#define BB 32
#define DIN 1024
#define DOUT 1024
#define BETA 0.9f
#define LEAK 0.9f

#define GRIDN 1024
#define NTHR 256

#define KT 32                  /* k per gemm tile */
#define NKS (DIN / KT)         /* 32 k-splits */
#define NBS 4                  /* b splits (8 b each) */
#define NJT 8                  /* j tiles of 128 */

/* output offsets (floats), in reference return order:
   s, E_W2, E_b2, Rh_W2, Rh_b2, g_bar2, r2 */
#define OFF_S  0
#define OFF_EW (BB * DOUT)
#define OFF_EB (OFF_EW + BB * DIN * DOUT)
#define OFF_RW (OFF_EB + BB * DOUT)
#define OFF_RB (OFF_RW + BB * DIN * DOUT)
#define OFF_G  (OFF_RB + BB * DOUT)
#define OFF_R  (OFF_G + BB * DOUT)

#define NVEC (BB * DIN * DOUT / 4)      /* 8388608 float4 */
#define CSTRIDE (GRIDN * NTHR)          /* 262144 */
#define NITER (NVEC / CSTRIDE)          /* 32 */

__device__ float g_hpart[NKS][BB * DOUT];   /* 4 MB scratch */
__device__ unsigned int g_c1, g_c2;         /* monotonic barrier counters */

/* wrap-safe, reset-free grid barrier (2^32 % 1024 == 0). */
__device__ __forceinline__ void grid_sync(unsigned int* cnt) {
    __syncthreads();
    if (threadIdx.x == 0) {
        __threadfence();
        const unsigned int prev = atomicAdd(cnt, 1u);
        const unsigned int target = prev - (prev % GRIDN) + GRIDN;
        volatile unsigned int* vc = (volatile unsigned int*)cnt;
        while ((int)(*vc - target) < 0) { __nanosleep(64); }
        __threadfence();
    }
    __syncthreads();
}

__global__ void __launch_bounds__(NTHR, 7)
fused_all(const float* __restrict__ x,
          const float* __restrict__ W,
          const float* __restrict__ bias,
          const float* __restrict__ u,
          const float4* __restrict__ E_W,
          const float* __restrict__ E_b,
          const float4* __restrict__ Rh_W,
          const float* __restrict__ Rh_b,
          const float* __restrict__ g_bar,
          const float* __restrict__ r,
          float* __restrict__ out) {
    __shared__ float ws[KT][128];   /* 16 KB: W tile 32k x 128j */
    __shared__ float xs[8][KT];     /* 1 KB: x tile 8b x 32k */

    const int bid = blockIdx.x;
    const int tid = threadIdx.x;

    /* ======== Phase A: split-K GEMM, (jt, ks, bs) = (8, 32, 4) ======== */
    {
        const int jt = bid & 7;
        const int ks = (bid >> 3) & 31;
        const int bs = bid >> 8;
        const int k0 = ks * KT;
        const int jb = jt * 128;
        const int b0 = bs * 8;

        /* W tile: 1024 float4, 4 per thread, coalesced */
#pragma unroll
        for (int i = 0; i < 4; i++) {
            const int f = i * 256 + tid;
            const int row = f >> 5;
            const int c4 = (f & 31) * 4;
            *(float4*)&ws[row][c4] = *(const float4*)&W[(k0 + row) * DOUT + jb + c4];
        }
        /* x tile: 64 float4 */
        if (tid < 64) {
            const int bb = tid >> 3;
            const int kq = (tid & 7) * 4;
            const float4 v = *(const float4*)&x[(b0 + bb) * DIN + k0 + kq];
            xs[bb][kq + 0] = v.x;
            xs[bb][kq + 1] = v.y;
            xs[bb][kq + 2] = v.z;
            xs[bb][kq + 3] = v.w;
        }
        __syncthreads();

        const int j4 = (tid & 31) * 4;   /* 4 j columns */
        const int bl = tid >> 5;         /* 1 local batch (0..7) */

        float4 acc = make_float4(0.f, 0.f, 0.f, 0.f);
#pragma unroll
        for (int kk = 0; kk < KT; kk++) {
            const float4 w = *(const float4*)&ws[kk][j4];
            const float xv = xs[bl][kk];
            acc.x = fmaf(xv, w.x, acc.x);
            acc.y = fmaf(xv, w.y, acc.y);
            acc.z = fmaf(xv, w.z, acc.z);
            acc.w = fmaf(xv, w.w, acc.w);
        }

        *(float4*)&g_hpart[ks][(b0 + bl) * DOUT + jb + j4] = acc;
    }

    grid_sync(&g_c1);

    /* ======== Phase B: activation + small outputs (blocks 0..31) ======== */
    if (bid < 32) {
        const int idx4 = bid * 256 + tid;    /* 0..8191 */
        const int bb = bid;                  /* idx4 >> 8 */
        const int j4 = tid;                  /* idx4 & 255 */

        float4 h = ((const float4*)bias)[j4];
#pragma unroll 8
        for (int ks = 0; ks < NKS; ks++) {
            const float4 p = __ldcg(&((const float4*)g_hpart[ks])[idx4]);
            h.x += p.x; h.y += p.y; h.z += p.z; h.w += p.w;
        }

        const float4 uu = ((const float4*)u)[idx4];
        const float4 eb = ((const float4*)E_b)[idx4];
        const float4 rb = ((const float4*)Rh_b)[idx4];
        const float4 gb = ((const float4*)g_bar)[idx4];

        const float ratio0 = LEAK * r[bb];
        const float r2 = ratio0 + 1.0f;
        const float ratio = ratio0 / r2;

        float4 so, ebo, rbo, go;
        {
            const float un = BETA * uu.x + h.x;
            const float s  = 1.0f / (1.0f + expf(-(un - 1.0f)));
            const float sg = s * (1.0f - s);
            const float a  = BETA * sg;
            so.x = s;
            const float eb1 = BETA * eb.x + 1.0f;
            ebo.x = BETA * eb1 + 1.0f;
            rbo.x = a * rb.x + (a * eb1 + sg);
            go.x  = ratio * gb.x + (1.0f - ratio) * a;
        }
        {
            const float un = BETA * uu.y + h.y;
            const float s  = 1.0f / (1.0f + expf(-(un - 1.0f)));
            const float sg = s * (1.0f - s);
            const float a  = BETA * sg;
            so.y = s;
            const float eb1 = BETA * eb.y + 1.0f;
            ebo.y = BETA * eb1 + 1.0f;
            rbo.y = a * rb.y + (a * eb1 + sg);
            go.y  = ratio * gb.y + (1.0f - ratio) * a;
        }
        {
            const float un = BETA * uu.z + h.z;
            const float s  = 1.0f / (1.0f + expf(-(un - 1.0f)));
            const float sg = s * (1.0f - s);
            const float a  = BETA * sg;
            so.z = s;
            const float eb1 = BETA * eb.z + 1.0f;
            ebo.z = BETA * eb1 + 1.0f;
            rbo.z = a * rb.z + (a * eb1 + sg);
            go.z  = ratio * gb.z + (1.0f - ratio) * a;
        }
        {
            const float un = BETA * uu.w + h.w;
            const float s  = 1.0f / (1.0f + expf(-(un - 1.0f)));
            const float sg = s * (1.0f - s);
            const float a  = BETA * sg;
            so.w = s;
            const float eb1 = BETA * eb.w + 1.0f;
            ebo.w = BETA * eb1 + 1.0f;
            rbo.w = a * rb.w + (a * eb1 + sg);
            go.w  = ratio * gb.w + (1.0f - ratio) * a;
        }

        ((float4*)(out + OFF_S))[idx4]  = so;
        ((float4*)(out + OFF_EB))[idx4] = ebo;
        ((float4*)(out + OFF_RB))[idx4] = rbo;
        ((float4*)(out + OFF_G))[idx4]  = go;
        if (j4 == 0) out[OFF_R + bb] = r2;
    }

    grid_sync(&g_c2);

    /* ======== Phase C: big streaming trace update ======== */
    {
        const float4* __restrict__ s4p = (const float4*)(out + OFF_S);
        float4* __restrict__ ew2 = (float4*)(out + OFF_EW);
        float4* __restrict__ rw2 = (float4*)(out + OFF_RW);

        const int base = bid * NTHR + tid;

#pragma unroll 1
        for (int it = 0; it < NITER; it++) {
            const int idx = it * CSTRIDE + base;
            const int bb  = idx >> 18;
            const int rem = idx & 262143;
            const int i   = rem >> 8;
            const int j4  = rem & 255;

            const float4 ew = __ldcs(&E_W[idx]);
            const float4 rh = __ldcs(&Rh_W[idx]);
            const float  xv = __ldg(&x[bb * DIN + i]);
            const float4 s4 = s4p[bb * 256 + j4];

            float4 o1, o2;
            {
                const float sg = s4.x * (1.0f - s4.x);
                const float a  = BETA * sg;
                const float e1 = fmaf(BETA, ew.x, xv);
                o1.x = fmaf(BETA, e1, xv);
                o2.x = fmaf(a, rh.x, fmaf(a, e1, xv * sg));
            }
            {
                const float sg = s4.y * (1.0f - s4.y);
                const float a  = BETA * sg;
                const float e1 = fmaf(BETA, ew.y, xv);
                o1.y = fmaf(BETA, e1, xv);
                o2.y = fmaf(a, rh.y, fmaf(a, e1, xv * sg));
            }
            {
                const float sg = s4.z * (1.0f - s4.z);
                const float a  = BETA * sg;
                const float e1 = fmaf(BETA, ew.z, xv);
                o1.z = fmaf(BETA, e1, xv);
                o2.z = fmaf(a, rh.z, fmaf(a, e1, xv * sg));
            }
            {
                const float sg = s4.w * (1.0f - s4.w);
                const float a  = BETA * sg;
                const float e1 = fmaf(BETA, ew.w, xv);
                o1.w = fmaf(BETA, e1, xv);
                o2.w = fmaf(a, rh.w, fmaf(a, e1, xv * sg));
            }

            __stcs(&ew2[idx], o1);
            __stcs(&rw2[idx], o2);
        }
    }
}

extern "C" void kernel_launch(void* const* d_in, const int* in_sizes, int n_in,
                              void* d_out, int out_size) {
    const float* x     = (const float*)d_in[0];
    const float* W     = (const float*)d_in[1];
    const float* bias  = (const float*)d_in[2];
    const float* u     = (const float*)d_in[3];
    const float* E_W   = (const float*)d_in[4];
    const float* E_b   = (const float*)d_in[5];
    const float* Rh_W  = (const float*)d_in[6];
    const float* Rh_b  = (const float*)d_in[7];
    const float* g_bar = (const float*)d_in[8];
    const float* r     = (const float*)d_in[9];
    float* out = (float*)d_out;

    fused_all<<<GRIDN, NTHR>>>(x, W, bias, u, (const float4*)E_W, E_b,
                               (const float4*)Rh_W, Rh_b, g_bar, r, out);
}